// round 14
// baseline (speedup 1.0000x reference)
#include <cuda_runtime.h>
#include <cuda_bf16.h>
#include <cstdint>
#include <math.h>

#define EXPERTS 8
#define HID     2048
#define INTER   1408
#define TOK     16384
#define I2      (2*INTER)

#define BM   128
#define BK   32
#define SSTB 80                        // smem row stride bytes (64B data + 16 pad)
#define TN1  44                        // INTER/32 (CTA covers 32 gate + 32 up cols)
#define TN2  32                        // HID/64 out-col tiles
#define A_BYTES (128*SSTB)             // 10240
#define B_BYTES (64*SSTB)              // 5120
#define B_OFFB  A_BYTES
#define STAGE_BYTES (A_BYTES + B_BYTES) // 15360
#define NSTAGE 4
#define SMEM_BYTES (NSTAGE*STAGE_BYTES) // 61440

// ---- scratch (alloc-free rule: __device__ globals) ----
__device__ __nv_bfloat16 g_xb[(size_t)TOK * HID];
__device__ __nv_bfloat16 g_w1[(size_t)EXPERTS * I2 * HID];
__device__ __nv_bfloat16 g_w2[(size_t)EXPERTS * HID * INTER];
__device__ __nv_bfloat16 g_h [(size_t)TOK * INTER];

// ---- helpers ----
__device__ __forceinline__ uint32_t smem_u32(const void* p) {
    uint32_t a;
    asm("{ .reg .u64 t; cvta.to.shared.u64 t, %1; cvt.u32.u64 %0, t; }" : "=r"(a) : "l"(p));
    return a;
}
__device__ __forceinline__ void cp16(uint32_t dst_smem, const void* src, int sz) {
    asm volatile("cp.async.cg.shared.global [%0], [%1], 16, %2;\n"
                 :: "r"(dst_smem), "l"(src), "r"(sz));
}
#define CP_COMMIT() asm volatile("cp.async.commit_group;\n")
#define CP_WAIT(n)  asm volatile("cp.async.wait_group %0;\n" :: "n"(n))

#define LDSM4(r, addr) \
    asm volatile("ldmatrix.sync.aligned.m8n8.x4.shared.b16 {%0,%1,%2,%3}, [%4];" \
        : "=r"((r)[0]), "=r"((r)[1]), "=r"((r)[2]), "=r"((r)[3]) : "r"(addr))

#define MMA(d, a, b) \
    asm volatile("mma.sync.aligned.m16n8k16.row.col.f32.bf16.bf16.f32 " \
        "{%0,%1,%2,%3},{%4,%5,%6,%7},{%8,%9},{%0,%1,%2,%3};\n" \
        : "+f"((d)[0]), "+f"((d)[1]), "+f"((d)[2]), "+f"((d)[3]) \
        : "r"((a)[0]), "r"((a)[1]), "r"((a)[2]), "r"((a)[3]), \
          "r"((b)[0]), "r"((b)[1]))

__device__ __forceinline__ float bround(float x) {
    return __bfloat162float(__float2bfloat16(x));
}

// Fragment set for one 64x32x16 warp slab
struct Frag {
    uint32_t a[4][4];
    uint32_t b[2][4];
};

__device__ __forceinline__ void ldfrag(Frag& f, uint32_t aBase, uint32_t bBase, int kk) {
    LDSM4(f.b[0], bBase + kk*32);
    LDSM4(f.b[1], bBase + 16*SSTB + kk*32);
    #pragma unroll
    for (int im = 0; im < 4; ++im)
        LDSM4(f.a[im], aBase + im*(16*SSTB) + kk*32);
}

__device__ __forceinline__ void mma_frag(float acc[4][4][4], const Frag& f) {
    #pragma unroll
    for (int im = 0; im < 4; ++im)
        #pragma unroll
        for (int p = 0; p < 2; ++p) {
            MMA(acc[im][2*p],   f.a[im], (&f.b[p][0]));
            MMA(acc[im][2*p+1], f.a[im], (&f.b[p][2]));
        }
}

// ---- fp32 -> bf16 conversion ----
__global__ void cvt_kernel(const float4* __restrict__ src, __nv_bfloat162* __restrict__ dst, int n4) {
    int i = blockIdx.x * blockDim.x + threadIdx.x;
    if (i >= n4) return;
    float4 v = src[i];
    dst[2*i]   = __floats2bfloat162_rn(v.x, v.y);
    dst[2*i+1] = __floats2bfloat162_rn(v.z, v.w);
}

// ---- GEMM1: h = silu(x@Wg^T) * (x@Wu^T), fused ----
// CTA: 128 rows x (32 gate | 32 up). B rows 0-31 gate(n0..), 32-63 up(INTER+n0..).
__global__ __launch_bounds__(128, 3) void gemm1_kernel(const int* __restrict__ counts) {
    extern __shared__ char dsm[];
    const int tid = threadIdx.x;

    int rem = blockIdx.x;
    int e = -1, off = 0, cnt = 0, tmi = 0, tni = 0;
    #pragma unroll
    for (int ee = 0; ee < EXPERTS; ++ee) {
        int c = counts[ee];
        int tm = (c + BM - 1) >> 7;
        int tiles = tm * TN1;
        if (e < 0) {
            if (rem < tiles) { e = ee; cnt = c; tmi = rem / TN1; tni = rem % TN1; }
            else             { rem -= tiles; off += c; }
        }
    }
    if (e < 0) return;
    const int m0 = tmi * BM;
    const int n0 = tni * 32;

    const __nv_bfloat16* Ag = g_xb + (size_t)off * HID;
    const __nv_bfloat16* Bg = g_w1 + (size_t)e * I2 * HID;

    const int warp = tid >> 5, lane = tid & 31;
    const int wm = warp >> 1, wn = warp & 1;        // 2 x 2 warps, 64x32 each
    const int g = lane >> 2, t = lane & 3;

    const uint32_t sb = smem_u32(dsm);
    const uint32_t aLane = (uint32_t)(wm*64 + (lane & 15))*SSTB + (lane >> 4)*16;
    const uint32_t bLane = B_OFFB + (uint32_t)(wn*32 + (lane >> 4)*8 + (lane & 7))*SSTB
                           + ((lane >> 3) & 1)*16;

    float acc[4][4][4];
    #pragma unroll
    for (int i = 0; i < 4; ++i)
        #pragma unroll
        for (int j = 0; j < 4; ++j)
            #pragma unroll
            for (int k = 0; k < 4; ++k) acc[i][j][k] = 0.f;

    auto issue = [&](int kt, int s) {
        const uint32_t base = sb + s * STAGE_BYTES;
        #pragma unroll
        for (int i = 0; i < 6; ++i) {              // 768 x 16B chunks / 128 thr
            int id = tid + i*128;
            if (id < 512) {                        // A: 128 rows x 4 chunks
                int row = id >> 2, kc = id & 3;
                int gm = m0 + row;
                int sz = (gm < cnt) ? 16 : 0;
                int gmc = (gm < cnt) ? gm : 0;
                cp16(base + row*SSTB + kc*16, Ag + (size_t)gmc*HID + kt*BK + kc*8, sz);
            } else {                               // B: 64 rows x 4 chunks
                int b = id - 512;
                int row = b >> 2, kc = b & 3;
                int gn = (row < 32) ? (n0 + row) : (INTER + n0 + row - 32);
                cp16(base + B_OFFB + row*SSTB + kc*16, Bg + (size_t)gn*HID + kt*BK + kc*8, 16);
            }
        }
    };

    const int KT = HID / BK;  // 64
    issue(0, 0); CP_COMMIT();
    issue(1, 1); CP_COMMIT();
    issue(2, 2); CP_COMMIT();
    CP_WAIT(1);                 // stages 0,1 landed
    __syncthreads();            // ... and visible block-wide

    Frag f0, f1;
    ldfrag(f0, sb + aLane, sb + bLane, 0);          // (kt=0, kk=0), stage 0
    int s_cur = 0;
    for (int kt = 0; kt < KT; ++kt) {
        const uint32_t stg = sb + s_cur * STAGE_BYTES;
        ldfrag(f1, stg + aLane, stg + bLane, 1);    // (kt, kk1) — stage kt visible
        mma_frag(acc, f0);
        int s_nxt = s_cur + 1; if (s_nxt == NSTAGE) s_nxt = 0;
        if (kt + 3 < KT) {
            int s_iss = s_cur - 1; if (s_iss < 0) s_iss = NSTAGE - 1;
            issue(kt + 3, s_iss);                   // writes stage kt-1: reads closed last barrier
        }
        CP_COMMIT();                                // cp issue overlaps mma f1 below
        if (kt + 1 < KT) {
            const uint32_t stg2 = sb + s_nxt * STAGE_BYTES;
            ldfrag(f0, stg2 + aLane, stg2 + bLane, 0);  // (kt+1, kk0) — stage kt+1 visible
        }
        mma_frag(acc, f1);
        CP_WAIT(1);                                 // groups <= kt+2 complete
        __syncthreads();                            // stage kt+2 visible; reads of stage kt closed
        s_cur = s_nxt;
    }

    // ---- epilogue: exchange bf16 gate tile, stepwise-bf16 silu (validated numerics) ----
    __nv_bfloat16* Cs = (__nv_bfloat16*)dsm;   // 128 x 40 bf16 = 10240 B
    if (wn == 0) {                              // gate holders: write bf16 gate
        #pragma unroll
        for (int im = 0; im < 4; ++im) {
            #pragma unroll
            for (int j = 0; j < 4; ++j) {
                int row = wm*64 + im*16 + g;
                int col = j*8 + t*2;
                *(__nv_bfloat162*)(Cs + (size_t)row*40 + col) =
                    __floats2bfloat162_rn(acc[im][j][0], acc[im][j][1]);
                *(__nv_bfloat162*)(Cs + (size_t)(row+8)*40 + col) =
                    __floats2bfloat162_rn(acc[im][j][2], acc[im][j][3]);
            }
        }
    }
    __syncthreads();
    if (wn == 1) {                              // up holders: bf16-round up, silu chain
        #pragma unroll
        for (int im = 0; im < 4; ++im) {
            #pragma unroll
            for (int j = 0; j < 4; ++j) {
                int row = wm*64 + im*16 + g;
                int col = j*8 + t*2;
                #pragma unroll
                for (int rr = 0; rr < 2; ++rr) {
                    int r = row + rr*8;
                    if (m0 + r < cnt) {
                        float u0 = bround(acc[im][j][rr*2+0]);
                        float u1 = bround(acc[im][j][rr*2+1]);
                        float g0 = __bfloat162float(Cs[(size_t)r*40 + col]);
                        float g1 = __bfloat162float(Cs[(size_t)r*40 + col + 1]);
                        float e0   = bround(expf(-g0));
                        float e1   = bround(expf(-g1));
                        float den0 = bround(1.f + e0);
                        float den1 = bround(1.f + e1);
                        float r0   = bround(1.f / den0);
                        float r1   = bround(1.f / den1);
                        float s0   = bround(g0 * r0);
                        float s1   = bround(g1 * r1);
                        *(__nv_bfloat162*)(g_h + (size_t)(off + m0 + r)*INTER + n0 + col) =
                            __floats2bfloat162_rn(s0 * u0, s1 * u1);
                    }
                }
            }
        }
    }
}

// ---- GEMM2: out = f32(bf16(h @ down^T)) ----
__global__ __launch_bounds__(128, 3) void gemm2_kernel(const int* __restrict__ counts,
                                                       float* __restrict__ out) {
    extern __shared__ char dsm[];
    const int tid = threadIdx.x;

    int rem = blockIdx.x;
    int e = -1, off = 0, cnt = 0, tmi = 0, tni = 0;
    #pragma unroll
    for (int ee = 0; ee < EXPERTS; ++ee) {
        int c = counts[ee];
        int tm = (c + BM - 1) >> 7;
        int tiles = tm * TN2;
        if (e < 0) {
            if (rem < tiles) { e = ee; cnt = c; tmi = rem / TN2; tni = rem % TN2; }
            else             { rem -= tiles; off += c; }
        }
    }
    if (e < 0) return;
    const int m0 = tmi * BM;
    const int n0 = tni * 64;

    const __nv_bfloat16* Ag = g_h  + (size_t)off * INTER;
    const __nv_bfloat16* Bg = g_w2 + (size_t)e * HID * INTER;

    const int warp = tid >> 5, lane = tid & 31;
    const int wm = warp >> 1, wn = warp & 1;
    const int g = lane >> 2, t = lane & 3;

    const uint32_t sb = smem_u32(dsm);
    const uint32_t aLane = (uint32_t)(wm*64 + (lane & 15))*SSTB + (lane >> 4)*16;
    const uint32_t bLane = B_OFFB + (uint32_t)(wn*32 + (lane >> 4)*8 + (lane & 7))*SSTB
                           + ((lane >> 3) & 1)*16;

    float acc[4][4][4];
    #pragma unroll
    for (int i = 0; i < 4; ++i)
        #pragma unroll
        for (int j = 0; j < 4; ++j)
            #pragma unroll
            for (int k = 0; k < 4; ++k) acc[i][j][k] = 0.f;

    auto issue = [&](int kt, int s) {
        const uint32_t base = sb + s * STAGE_BYTES;
        #pragma unroll
        for (int i = 0; i < 6; ++i) {
            int id = tid + i*128;
            if (id < 512) {
                int row = id >> 2, kc = id & 3;
                int gm = m0 + row;
                int sz = (gm < cnt) ? 16 : 0;
                int gmc = (gm < cnt) ? gm : 0;
                cp16(base + row*SSTB + kc*16, Ag + (size_t)gmc*INTER + kt*BK + kc*8, sz);
            } else {
                int b = id - 512;
                int row = b >> 2, kc = b & 3;
                cp16(base + B_OFFB + row*SSTB + kc*16,
                     Bg + (size_t)(n0 + row)*INTER + kt*BK + kc*8, 16);
            }
        }
    };

    const int KT = INTER / BK;  // 44
    issue(0, 0); CP_COMMIT();
    issue(1, 1); CP_COMMIT();
    issue(2, 2); CP_COMMIT();
    CP_WAIT(1);
    __syncthreads();

    Frag f0, f1;
    ldfrag(f0, sb + aLane, sb + bLane, 0);
    int s_cur = 0;
    for (int kt = 0; kt < KT; ++kt) {
        const uint32_t stg = sb + s_cur * STAGE_BYTES;
        ldfrag(f1, stg + aLane, stg + bLane, 1);
        mma_frag(acc, f0);
        int s_nxt = s_cur + 1; if (s_nxt == NSTAGE) s_nxt = 0;
        if (kt + 3 < KT) {
            int s_iss = s_cur - 1; if (s_iss < 0) s_iss = NSTAGE - 1;
            issue(kt + 3, s_iss);
        }
        CP_COMMIT();
        if (kt + 1 < KT) {
            const uint32_t stg2 = sb + s_nxt * STAGE_BYTES;
            ldfrag(f0, stg2 + aLane, stg2 + bLane, 0);
        }
        mma_frag(acc, f1);
        CP_WAIT(1);
        __syncthreads();
        s_cur = s_nxt;
    }

    // epilogue: round to bf16 then exact f32 upcast (validated numerics)
    #pragma unroll
    for (int im = 0; im < 4; ++im) {
        #pragma unroll
        for (int j = 0; j < 4; ++j) {
            int lm  = wm*64 + im*16 + g;
            int col = n0 + wn*32 + j*8 + t*2;
            if (m0 + lm < cnt) {
                float2* p = (float2*)(out + (size_t)(off + m0 + lm)*HID + col);
                *p = make_float2(bround(acc[im][j][0]), bround(acc[im][j][1]));
            }
            if (m0 + lm + 8 < cnt) {
                float2* p = (float2*)(out + (size_t)(off + m0 + lm + 8)*HID + col);
                *p = make_float2(bround(acc[im][j][2]), bround(acc[im][j][3]));
            }
        }
    }
}

extern "C" void kernel_launch(void* const* d_in, const int* in_sizes, int n_in,
                              void* d_out, int out_size) {
    const float* x      = (const float*)d_in[0];
    const float* w1     = (const float*)d_in[1];
    const float* w2     = (const float*)d_in[2];
    const int*   counts = (const int*)d_in[3];
    float*       out    = (float*)d_out;

    void *pxb, *pw1, *pw2;
    cudaGetSymbolAddress(&pxb, g_xb);
    cudaGetSymbolAddress(&pw1, g_w1);
    cudaGetSymbolAddress(&pw2, g_w2);

    cudaFuncSetAttribute(gemm1_kernel, cudaFuncAttributeMaxDynamicSharedMemorySize, SMEM_BYTES);
    cudaFuncSetAttribute(gemm2_kernel, cudaFuncAttributeMaxDynamicSharedMemorySize, SMEM_BYTES);

    const int n4x  = (TOK * HID) / 4;
    const int n4w1 = (EXPERTS * I2 * HID) / 4;
    const int n4w2 = (EXPERTS * HID * INTER) / 4;
    cvt_kernel<<<(n4x  + 255) / 256, 256>>>((const float4*)x,  (__nv_bfloat162*)pxb, n4x);
    cvt_kernel<<<(n4w1 + 255) / 256, 256>>>((const float4*)w1, (__nv_bfloat162*)pw1, n4w1);
    cvt_kernel<<<(n4w2 + 255) / 256, 256>>>((const float4*)w2, (__nv_bfloat162*)pw2, n4w2);

    const int maxtm = TOK / BM + EXPERTS;   // 136
    gemm1_kernel<<<maxtm * TN1, 128, SMEM_BYTES>>>(counts);
    gemm2_kernel<<<maxtm * TN2, 128, SMEM_BYTES>>>(counts, out);
}

// round 15
// speedup vs baseline: 1.1451x; 1.1451x over previous
#include <cuda_runtime.h>
#include <cuda_bf16.h>
#include <cstdint>
#include <math.h>

#define EXPERTS 8
#define HID     2048
#define INTER   1408
#define TOK     16384
#define I2      (2*INTER)

#define BM   128
#define BK   32
#define SSTB 80                        // smem row stride bytes (64B data + 16 pad)
#define TN1  22                        // INTER/64 (CTA covers 64 gate + 64 up cols)
#define TN2  16                        // HID/128 out-col tiles
#define A_BYTES (128*SSTB)             // 10240
#define B_BYTES (128*SSTB)             // 10240
#define B_OFFB  A_BYTES
#define STAGE_BYTES (A_BYTES + B_BYTES) // 20480
#define NSTAGE 5
#define SMEM_BYTES (NSTAGE*STAGE_BYTES) // 102400

// ---- scratch (alloc-free rule: __device__ globals) ----
__device__ __nv_bfloat16 g_xb[(size_t)TOK * HID];
__device__ __nv_bfloat16 g_w1[(size_t)EXPERTS * I2 * HID];
__device__ __nv_bfloat16 g_w2[(size_t)EXPERTS * HID * INTER];
__device__ __nv_bfloat16 g_h [(size_t)TOK * INTER];

// ---- helpers ----
__device__ __forceinline__ uint32_t smem_u32(const void* p) {
    uint32_t a;
    asm("{ .reg .u64 t; cvta.to.shared.u64 t, %1; cvt.u32.u64 %0, t; }" : "=r"(a) : "l"(p));
    return a;
}
__device__ __forceinline__ void cp16(uint32_t dst_smem, const void* src, int sz) {
    asm volatile("cp.async.cg.shared.global [%0], [%1], 16, %2;\n"
                 :: "r"(dst_smem), "l"(src), "r"(sz));
}
#define CP_COMMIT() asm volatile("cp.async.commit_group;\n")
#define CP_WAIT(n)  asm volatile("cp.async.wait_group %0;\n" :: "n"(n))

#define LDSM4(r, addr) \
    asm volatile("ldmatrix.sync.aligned.m8n8.x4.shared.b16 {%0,%1,%2,%3}, [%4];" \
        : "=r"((r)[0]), "=r"((r)[1]), "=r"((r)[2]), "=r"((r)[3]) : "r"(addr))

#define MMA(d, a, b) \
    asm volatile("mma.sync.aligned.m16n8k16.row.col.f32.bf16.bf16.f32 " \
        "{%0,%1,%2,%3},{%4,%5,%6,%7},{%8,%9},{%0,%1,%2,%3};\n" \
        : "+f"((d)[0]), "+f"((d)[1]), "+f"((d)[2]), "+f"((d)[3]) \
        : "r"((a)[0]), "r"((a)[1]), "r"((a)[2]), "r"((a)[3]), \
          "r"((b)[0]), "r"((b)[1]))

__device__ __forceinline__ float bround(float x) {
    return __bfloat162float(__float2bfloat16(x));
}

// Fragment set for one 64x64x16 warp slab
struct Frag {
    uint32_t a[4][4];
    uint32_t b[4][4];
};

__device__ __forceinline__ void ldfrag(Frag& f, uint32_t aBase, uint32_t bBase, int kk) {
    #pragma unroll
    for (int p = 0; p < 4; ++p)
        LDSM4(f.b[p], bBase + p*(16*SSTB) + kk*32);
    #pragma unroll
    for (int im = 0; im < 4; ++im)
        LDSM4(f.a[im], aBase + im*(16*SSTB) + kk*32);
}

__device__ __forceinline__ void mma_frag(float acc[4][8][4], const Frag& f) {
    #pragma unroll
    for (int im = 0; im < 4; ++im)
        #pragma unroll
        for (int p = 0; p < 4; ++p) {
            MMA(acc[im][2*p],   f.a[im], (&f.b[p][0]));
            MMA(acc[im][2*p+1], f.a[im], (&f.b[p][2]));
        }
}

// ---- fp32 -> bf16 conversion ----
__global__ void cvt_kernel(const float4* __restrict__ src, __nv_bfloat162* __restrict__ dst, int n4) {
    int i = blockIdx.x * blockDim.x + threadIdx.x;
    if (i >= n4) return;
    float4 v = src[i];
    dst[2*i]   = __floats2bfloat162_rn(v.x, v.y);
    dst[2*i+1] = __floats2bfloat162_rn(v.z, v.w);
}

// ---- GEMM1: h = silu(x@Wg^T) * (x@Wu^T), fused ----
__global__ __launch_bounds__(128, 2) void gemm1_kernel(const int* __restrict__ counts) {
    extern __shared__ char dsm[];
    const int tid = threadIdx.x;

    int rem = blockIdx.x;
    int e = -1, off = 0, cnt = 0, tmi = 0, tni = 0;
    #pragma unroll
    for (int ee = 0; ee < EXPERTS; ++ee) {
        int c = counts[ee];
        int tm = (c + BM - 1) >> 7;
        int tiles = tm * TN1;
        if (e < 0) {
            if (rem < tiles) { e = ee; cnt = c; tmi = rem / TN1; tni = rem % TN1; }
            else             { rem -= tiles; off += c; }
        }
    }
    if (e < 0) return;
    const int m0 = tmi * BM;
    const int n0 = tni * 64;

    const __nv_bfloat16* Ag = g_xb + (size_t)off * HID;
    const __nv_bfloat16* Bg = g_w1 + (size_t)e * I2 * HID;

    const int warp = tid >> 5, lane = tid & 31;
    const int wm = warp >> 1, wn = warp & 1;        // 2 x 2 warps, 64x64 each
    const int g = lane >> 2, t = lane & 3;

    const uint32_t sb = smem_u32(dsm);
    const uint32_t aLane = (uint32_t)(wm*64 + (lane & 15))*SSTB + (lane >> 4)*16;
    const uint32_t bLane = B_OFFB + (uint32_t)(wn*64 + (lane >> 4)*8 + (lane & 7))*SSTB
                           + ((lane >> 3) & 1)*16;

    float acc[4][8][4];
    #pragma unroll
    for (int i = 0; i < 4; ++i)
        #pragma unroll
        for (int j = 0; j < 8; ++j)
            #pragma unroll
            for (int k = 0; k < 4; ++k) acc[i][j][k] = 0.f;

    auto issue = [&](int kt, int s) {
        const uint32_t base = sb + s * STAGE_BYTES;
        #pragma unroll
        for (int i = 0; i < 8; ++i) {              // 1024 x 16B chunks / 128 thr
            int id = tid + i*128;
            if (id < 512) {                        // A: 128 rows x 4 chunks
                int row = id >> 2, kc = id & 3;
                int gm = m0 + row;
                int sz = (gm < cnt) ? 16 : 0;
                int gmc = (gm < cnt) ? gm : 0;
                cp16(base + row*SSTB + kc*16, Ag + (size_t)gmc*HID + kt*BK + kc*8, sz);
            } else {                               // B: 128 rows x 4 chunks
                int b = id - 512;
                int row = b >> 2, kc = b & 3;
                int gn = (row < 64) ? (n0 + row) : (INTER + n0 + row - 64);
                cp16(base + B_OFFB + row*SSTB + kc*16, Bg + (size_t)gn*HID + kt*BK + kc*8, 16);
            }
        }
    };

    const int KT = HID / BK;  // 64
    issue(0, 0); CP_COMMIT();
    issue(1, 1); CP_COMMIT();
    issue(2, 2); CP_COMMIT();
    issue(3, 3); CP_COMMIT();
    CP_WAIT(2);                 // stages 0,1 landed
    __syncthreads();            // ... and visible block-wide

    Frag f0, f1;
    ldfrag(f0, sb + aLane, sb + bLane, 0);          // (kt=0, kk=0), stage 0
    int s_cur = 0;
    for (int kt = 0; kt < KT; ++kt) {
        const uint32_t stg = sb + s_cur * STAGE_BYTES;
        ldfrag(f1, stg + aLane, stg + bLane, 1);    // (kt, kk1) — stage kt visible
        mma_frag(acc, f0);
        int s_nxt = s_cur + 1; if (s_nxt == NSTAGE) s_nxt = 0;
        if (kt + 4 < KT) {
            int s_iss = s_cur - 1; if (s_iss < 0) s_iss = NSTAGE - 1;
            issue(kt + 4, s_iss);                   // writes stage kt-1: reads closed at iter kt-1 barrier
        }
        CP_COMMIT();
        CP_WAIT(2);                                 // groups <= kt+2 complete
        __syncthreads();                            // barrier hides behind f0's draining HMMAs
        if (kt + 1 < KT) {
            const uint32_t stg2 = sb + s_nxt * STAGE_BYTES;
            ldfrag(f0, stg2 + aLane, stg2 + bLane, 0);  // (kt+1, kk0) — stage kt+1 visible
        }
        mma_frag(acc, f1);                          // flows into next iter head, no sync between
        s_cur = s_nxt;
    }
    __syncthreads();

    // ---- epilogue: exchange bf16 gate tile, stepwise-bf16 silu (validated numerics) ----
    __nv_bfloat16* Cs = (__nv_bfloat16*)dsm;   // 128 x 72 bf16 = 18432 B
    if (wn == 0) {                              // gate holders: write bf16 gate
        #pragma unroll
        for (int im = 0; im < 4; ++im) {
            #pragma unroll
            for (int j = 0; j < 8; ++j) {
                int row = wm*64 + im*16 + g;
                int col = j*8 + t*2;
                *(__nv_bfloat162*)(Cs + (size_t)row*72 + col) =
                    __floats2bfloat162_rn(acc[im][j][0], acc[im][j][1]);
                *(__nv_bfloat162*)(Cs + (size_t)(row+8)*72 + col) =
                    __floats2bfloat162_rn(acc[im][j][2], acc[im][j][3]);
            }
        }
    }
    __syncthreads();
    if (wn == 1) {                              // up holders: bf16-round up, silu chain
        #pragma unroll
        for (int im = 0; im < 4; ++im) {
            #pragma unroll
            for (int j = 0; j < 8; ++j) {
                int row = wm*64 + im*16 + g;
                int col = j*8 + t*2;
                #pragma unroll
                for (int rr = 0; rr < 2; ++rr) {
                    int r = row + rr*8;
                    if (m0 + r < cnt) {
                        float u0 = bround(acc[im][j][rr*2+0]);
                        float u1 = bround(acc[im][j][rr*2+1]);
                        float g0 = __bfloat162float(Cs[(size_t)r*72 + col]);
                        float g1 = __bfloat162float(Cs[(size_t)r*72 + col + 1]);
                        float e0   = bround(expf(-g0));
                        float e1   = bround(expf(-g1));
                        float den0 = bround(1.f + e0);
                        float den1 = bround(1.f + e1);
                        float r0   = bround(1.f / den0);
                        float r1   = bround(1.f / den1);
                        float s0   = bround(g0 * r0);
                        float s1   = bround(g1 * r1);
                        *(__nv_bfloat162*)(g_h + (size_t)(off + m0 + r)*INTER + n0 + col) =
                            __floats2bfloat162_rn(s0 * u0, s1 * u1);
                    }
                }
            }
        }
    }
}

// ---- GEMM2: out = f32(bf16(h @ down^T)) ----
__global__ __launch_bounds__(128, 2) void gemm2_kernel(const int* __restrict__ counts,
                                                       float* __restrict__ out) {
    extern __shared__ char dsm[];
    const int tid = threadIdx.x;

    int rem = blockIdx.x;
    int e = -1, off = 0, cnt = 0, tmi = 0, tni = 0;
    #pragma unroll
    for (int ee = 0; ee < EXPERTS; ++ee) {
        int c = counts[ee];
        int tm = (c + BM - 1) >> 7;
        int tiles = tm * TN2;
        if (e < 0) {
            if (rem < tiles) { e = ee; cnt = c; tmi = rem / TN2; tni = rem % TN2; }
            else             { rem -= tiles; off += c; }
        }
    }
    if (e < 0) return;
    const int m0 = tmi * BM;
    const int n0 = tni * 128;

    const __nv_bfloat16* Ag = g_h  + (size_t)off * INTER;
    const __nv_bfloat16* Bg = g_w2 + (size_t)e * HID * INTER;

    const int warp = tid >> 5, lane = tid & 31;
    const int wm = warp >> 1, wn = warp & 1;
    const int g = lane >> 2, t = lane & 3;

    const uint32_t sb = smem_u32(dsm);
    const uint32_t aLane = (uint32_t)(wm*64 + (lane & 15))*SSTB + (lane >> 4)*16;
    const uint32_t bLane = B_OFFB + (uint32_t)(wn*64 + (lane >> 4)*8 + (lane & 7))*SSTB
                           + ((lane >> 3) & 1)*16;

    float acc[4][8][4];
    #pragma unroll
    for (int i = 0; i < 4; ++i)
        #pragma unroll
        for (int j = 0; j < 8; ++j)
            #pragma unroll
            for (int k = 0; k < 4; ++k) acc[i][j][k] = 0.f;

    auto issue = [&](int kt, int s) {
        const uint32_t base = sb + s * STAGE_BYTES;
        #pragma unroll
        for (int i = 0; i < 8; ++i) {
            int id = tid + i*128;
            if (id < 512) {
                int row = id >> 2, kc = id & 3;
                int gm = m0 + row;
                int sz = (gm < cnt) ? 16 : 0;
                int gmc = (gm < cnt) ? gm : 0;
                cp16(base + row*SSTB + kc*16, Ag + (size_t)gmc*INTER + kt*BK + kc*8, sz);
            } else {
                int b = id - 512;
                int row = b >> 2, kc = b & 3;
                cp16(base + B_OFFB + row*SSTB + kc*16,
                     Bg + (size_t)(n0 + row)*INTER + kt*BK + kc*8, 16);
            }
        }
    };

    const int KT = INTER / BK;  // 44
    issue(0, 0); CP_COMMIT();
    issue(1, 1); CP_COMMIT();
    issue(2, 2); CP_COMMIT();
    issue(3, 3); CP_COMMIT();
    CP_WAIT(2);
    __syncthreads();

    Frag f0, f1;
    ldfrag(f0, sb + aLane, sb + bLane, 0);
    int s_cur = 0;
    for (int kt = 0; kt < KT; ++kt) {
        const uint32_t stg = sb + s_cur * STAGE_BYTES;
        ldfrag(f1, stg + aLane, stg + bLane, 1);
        mma_frag(acc, f0);
        int s_nxt = s_cur + 1; if (s_nxt == NSTAGE) s_nxt = 0;
        if (kt + 4 < KT) {
            int s_iss = s_cur - 1; if (s_iss < 0) s_iss = NSTAGE - 1;
            issue(kt + 4, s_iss);
        }
        CP_COMMIT();
        CP_WAIT(2);
        __syncthreads();
        if (kt + 1 < KT) {
            const uint32_t stg2 = sb + s_nxt * STAGE_BYTES;
            ldfrag(f0, stg2 + aLane, stg2 + bLane, 0);
        }
        mma_frag(acc, f1);
        s_cur = s_nxt;
    }

    // epilogue: round to bf16 then exact f32 upcast (validated numerics)
    #pragma unroll
    for (int im = 0; im < 4; ++im) {
        #pragma unroll
        for (int j = 0; j < 8; ++j) {
            int lm  = wm*64 + im*16 + g;
            int col = n0 + wn*64 + j*8 + t*2;
            if (m0 + lm < cnt) {
                float2* p = (float2*)(out + (size_t)(off + m0 + lm)*HID + col);
                *p = make_float2(bround(acc[im][j][0]), bround(acc[im][j][1]));
            }
            if (m0 + lm + 8 < cnt) {
                float2* p = (float2*)(out + (size_t)(off + m0 + lm + 8)*HID + col);
                *p = make_float2(bround(acc[im][j][2]), bround(acc[im][j][3]));
            }
        }
    }
}

extern "C" void kernel_launch(void* const* d_in, const int* in_sizes, int n_in,
                              void* d_out, int out_size) {
    const float* x      = (const float*)d_in[0];
    const float* w1     = (const float*)d_in[1];
    const float* w2     = (const float*)d_in[2];
    const int*   counts = (const int*)d_in[3];
    float*       out    = (float*)d_out;

    void *pxb, *pw1, *pw2;
    cudaGetSymbolAddress(&pxb, g_xb);
    cudaGetSymbolAddress(&pw1, g_w1);
    cudaGetSymbolAddress(&pw2, g_w2);

    cudaFuncSetAttribute(gemm1_kernel, cudaFuncAttributeMaxDynamicSharedMemorySize, SMEM_BYTES);
    cudaFuncSetAttribute(gemm2_kernel, cudaFuncAttributeMaxDynamicSharedMemorySize, SMEM_BYTES);

    const int n4x  = (TOK * HID) / 4;
    const int n4w1 = (EXPERTS * I2 * HID) / 4;
    const int n4w2 = (EXPERTS * HID * INTER) / 4;
    cvt_kernel<<<(n4x  + 255) / 256, 256>>>((const float4*)x,  (__nv_bfloat162*)pxb, n4x);
    cvt_kernel<<<(n4w1 + 255) / 256, 256>>>((const float4*)w1, (__nv_bfloat162*)pw1, n4w1);
    cvt_kernel<<<(n4w2 + 255) / 256, 256>>>((const float4*)w2, (__nv_bfloat162*)pw2, n4w2);

    const int maxtm = TOK / BM + EXPERTS;   // 136
    gemm1_kernel<<<maxtm * TN1, 128, SMEM_BYTES>>>(counts);
    gemm2_kernel<<<maxtm * TN2, 128, SMEM_BYTES>>>(counts, out);
}

// round 16
// speedup vs baseline: 1.2040x; 1.0514x over previous
#include <cuda_runtime.h>
#include <cuda_bf16.h>
#include <cstdint>
#include <math.h>

#define EXPERTS 8
#define HID     2048
#define INTER   1408
#define TOK     16384
#define I2      (2*INTER)

#define BM   128
#define BK   32
#define SSTB 80                        // smem row stride bytes (64B data + 16 pad)
#define TN1  22                        // INTER/64 (CTA covers 64 gate + 64 up cols)
#define TN2  16                        // HID/128 out-col tiles
#define A_BYTES (128*SSTB)             // 10240
#define B_BYTES (128*SSTB)             // 10240
#define B_OFFB  A_BYTES
#define STAGE_BYTES (A_BYTES + B_BYTES) // 20480
#define NSTAGE 5
#define SMEM_BYTES (NSTAGE*STAGE_BYTES) // 102400

// ---- scratch (alloc-free rule: __device__ globals) ----
__device__ __nv_bfloat16 g_xb[(size_t)TOK * HID];
__device__ __nv_bfloat16 g_w1[(size_t)EXPERTS * I2 * HID];
__device__ __nv_bfloat16 g_w2[(size_t)EXPERTS * HID * INTER];
__device__ __nv_bfloat16 g_h [(size_t)TOK * INTER];

// ---- helpers ----
__device__ __forceinline__ uint32_t smem_u32(const void* p) {
    uint32_t a;
    asm("{ .reg .u64 t; cvta.to.shared.u64 t, %1; cvt.u32.u64 %0, t; }" : "=r"(a) : "l"(p));
    return a;
}
__device__ __forceinline__ void cp16(uint32_t dst_smem, const void* src, int sz) {
    asm volatile("cp.async.cg.shared.global [%0], [%1], 16, %2;\n"
                 :: "r"(dst_smem), "l"(src), "r"(sz));
}
#define CP_COMMIT() asm volatile("cp.async.commit_group;\n")
#define CP_WAIT(n)  asm volatile("cp.async.wait_group %0;\n" :: "n"(n))

#define LDSM4(r, addr) \
    asm volatile("ldmatrix.sync.aligned.m8n8.x4.shared.b16 {%0,%1,%2,%3}, [%4];" \
        : "=r"((r)[0]), "=r"((r)[1]), "=r"((r)[2]), "=r"((r)[3]) : "r"(addr))

#define MMA(d, a, b) \
    asm volatile("mma.sync.aligned.m16n8k16.row.col.f32.bf16.bf16.f32 " \
        "{%0,%1,%2,%3},{%4,%5,%6,%7},{%8,%9},{%0,%1,%2,%3};\n" \
        : "+f"((d)[0]), "+f"((d)[1]), "+f"((d)[2]), "+f"((d)[3]) \
        : "r"((a)[0]), "r"((a)[1]), "r"((a)[2]), "r"((a)[3]), \
          "r"((b)[0]), "r"((b)[1]))

__device__ __forceinline__ float bround(float x) {
    return __bfloat162float(__float2bfloat16(x));
}

// Fragment set for one 64x64x16 warp slab
struct Frag {
    uint32_t a[4][4];
    uint32_t b[4][4];
};

__device__ __forceinline__ void ldfrag(Frag& f, uint32_t aBase, uint32_t bBase, int kk) {
    #pragma unroll
    for (int p = 0; p < 4; ++p)
        LDSM4(f.b[p], bBase + p*(16*SSTB) + kk*32);
    #pragma unroll
    for (int im = 0; im < 4; ++im)
        LDSM4(f.a[im], aBase + im*(16*SSTB) + kk*32);
}

__device__ __forceinline__ void mma_frag(float acc[4][8][4], const Frag& f) {
    #pragma unroll
    for (int im = 0; im < 4; ++im)
        #pragma unroll
        for (int p = 0; p < 4; ++p) {
            MMA(acc[im][2*p],   f.a[im], (&f.b[p][0]));
            MMA(acc[im][2*p+1], f.a[im], (&f.b[p][2]));
        }
}

// ---- fp32 -> bf16 conversion ----
__global__ void cvt_kernel(const float4* __restrict__ src, __nv_bfloat162* __restrict__ dst, int n4) {
    int i = blockIdx.x * blockDim.x + threadIdx.x;
    if (i >= n4) return;
    float4 v = src[i];
    dst[2*i]   = __floats2bfloat162_rn(v.x, v.y);
    dst[2*i+1] = __floats2bfloat162_rn(v.z, v.w);
}

// ---- GEMM1: h = silu(x@Wg^T) * (x@Wu^T), fused ----
__global__ __launch_bounds__(128, 2) void gemm1_kernel(const int* __restrict__ counts) {
    extern __shared__ char dsm[];
    const int tid = threadIdx.x;

    int rem = blockIdx.x;
    int e = -1, off = 0, cnt = 0, tmi = 0, tni = 0;
    #pragma unroll
    for (int ee = 0; ee < EXPERTS; ++ee) {
        int c = counts[ee];
        int tm = (c + BM - 1) >> 7;
        int tiles = tm * TN1;
        if (e < 0) {
            if (rem < tiles) { e = ee; cnt = c; tmi = rem / TN1; tni = rem % TN1; }
            else             { rem -= tiles; off += c; }
        }
    }
    if (e < 0) return;
    const int m0 = tmi * BM;
    const int n0 = tni * 64;

    const __nv_bfloat16* Ag = g_xb + (size_t)off * HID;
    const __nv_bfloat16* Bg = g_w1 + (size_t)e * I2 * HID;

    const int warp = tid >> 5, lane = tid & 31;
    const int wm = warp >> 1, wn = warp & 1;        // 2 x 2 warps, 64x64 each
    const int g = lane >> 2, t = lane & 3;

    const uint32_t sb = smem_u32(dsm);
    const uint32_t aLane = (uint32_t)(wm*64 + (lane & 15))*SSTB + (lane >> 4)*16;
    const uint32_t bLane = B_OFFB + (uint32_t)(wn*64 + (lane >> 4)*8 + (lane & 7))*SSTB
                           + ((lane >> 3) & 1)*16;

    float acc[4][8][4];
    #pragma unroll
    for (int i = 0; i < 4; ++i)
        #pragma unroll
        for (int j = 0; j < 8; ++j)
            #pragma unroll
            for (int k = 0; k < 4; ++k) acc[i][j][k] = 0.f;

    auto issue = [&](int kt, int s) {
        const uint32_t base = sb + s * STAGE_BYTES;
        #pragma unroll
        for (int i = 0; i < 8; ++i) {              // 1024 x 16B chunks / 128 thr
            int id = tid + i*128;
            if (id < 512) {                        // A: 128 rows x 4 chunks
                int row = id >> 2, kc = id & 3;
                int gm = m0 + row;
                int sz = (gm < cnt) ? 16 : 0;
                int gmc = (gm < cnt) ? gm : 0;
                cp16(base + row*SSTB + kc*16, Ag + (size_t)gmc*HID + kt*BK + kc*8, sz);
            } else {                               // B: 128 rows x 4 chunks
                int b = id - 512;
                int row = b >> 2, kc = b & 3;
                int gn = (row < 64) ? (n0 + row) : (INTER + n0 + row - 64);
                cp16(base + B_OFFB + row*SSTB + kc*16, Bg + (size_t)gn*HID + kt*BK + kc*8, 16);
            }
        }
    };

    const int KT = HID / BK;  // 64
    issue(0, 0); CP_COMMIT();
    issue(1, 1); CP_COMMIT();
    issue(2, 2); CP_COMMIT();
    issue(3, 3); CP_COMMIT();
    CP_WAIT(2);                 // stages 0,1 landed
    __syncthreads();            // ... and visible block-wide

    Frag f0, f1;
    ldfrag(f0, sb + aLane, sb + bLane, 0);          // (kt=0, kk=0), stage 0
    int s_cur = 0;
    for (int kt = 0; kt < KT; ++kt) {
        const uint32_t stg = sb + s_cur * STAGE_BYTES;
        ldfrag(f1, stg + aLane, stg + bLane, 1);    // (kt, kk1) — stage kt visible
        mma_frag(acc, f0);
        int s_nxt = s_cur + 1; if (s_nxt == NSTAGE) s_nxt = 0;
        if (kt + 4 < KT) {
            int s_iss = s_cur - 1; if (s_iss < 0) s_iss = NSTAGE - 1;
            issue(kt + 4, s_iss);                   // writes stage kt-1: reads closed last barrier
        }
        CP_COMMIT();                                // cp issue overlaps mma f1 below
        if (kt + 1 < KT) {
            const uint32_t stg2 = sb + s_nxt * STAGE_BYTES;
            ldfrag(f0, stg2 + aLane, stg2 + bLane, 0);  // (kt+1, kk0) — stage kt+1 visible
        }
        mma_frag(acc, f1);
        CP_WAIT(2);                                 // groups <= kt+2 complete
        __syncthreads();                            // stage kt+2 visible; reads of stage kt closed
        s_cur = s_nxt;
    }

    // ---- epilogue: exchange bf16 gate tile, stepwise-bf16 silu (validated numerics) ----
    __nv_bfloat16* Cs = (__nv_bfloat16*)dsm;   // 128 x 72 bf16 = 18432 B
    if (wn == 0) {                              // gate holders: write bf16 gate
        #pragma unroll
        for (int im = 0; im < 4; ++im) {
            #pragma unroll
            for (int j = 0; j < 8; ++j) {
                int row = wm*64 + im*16 + g;
                int col = j*8 + t*2;
                *(__nv_bfloat162*)(Cs + (size_t)row*72 + col) =
                    __floats2bfloat162_rn(acc[im][j][0], acc[im][j][1]);
                *(__nv_bfloat162*)(Cs + (size_t)(row+8)*72 + col) =
                    __floats2bfloat162_rn(acc[im][j][2], acc[im][j][3]);
            }
        }
    }
    __syncthreads();
    if (wn == 1) {                              // up holders: bf16-round up, silu chain
        #pragma unroll
        for (int im = 0; im < 4; ++im) {
            #pragma unroll
            for (int j = 0; j < 8; ++j) {
                int row = wm*64 + im*16 + g;
                int col = j*8 + t*2;
                #pragma unroll
                for (int rr = 0; rr < 2; ++rr) {
                    int r = row + rr*8;
                    if (m0 + r < cnt) {
                        float u0 = bround(acc[im][j][rr*2+0]);
                        float u1 = bround(acc[im][j][rr*2+1]);
                        float g0 = __bfloat162float(Cs[(size_t)r*72 + col]);
                        float g1 = __bfloat162float(Cs[(size_t)r*72 + col + 1]);
                        float e0   = bround(expf(-g0));
                        float e1   = bround(expf(-g1));
                        float den0 = bround(1.f + e0);
                        float den1 = bround(1.f + e1);
                        float r0   = bround(1.f / den0);
                        float r1   = bround(1.f / den1);
                        float s0   = bround(g0 * r0);
                        float s1   = bround(g1 * r1);
                        *(__nv_bfloat162*)(g_h + (size_t)(off + m0 + r)*INTER + n0 + col) =
                            __floats2bfloat162_rn(s0 * u0, s1 * u1);
                    }
                }
            }
        }
    }
}

// ---- GEMM2: out = f32(bf16(h @ down^T)) ----
__global__ __launch_bounds__(128, 2) void gemm2_kernel(const int* __restrict__ counts,
                                                       float* __restrict__ out) {
    extern __shared__ char dsm[];
    const int tid = threadIdx.x;

    int rem = blockIdx.x;
    int e = -1, off = 0, cnt = 0, tmi = 0, tni = 0;
    #pragma unroll
    for (int ee = 0; ee < EXPERTS; ++ee) {
        int c = counts[ee];
        int tm = (c + BM - 1) >> 7;
        int tiles = tm * TN2;
        if (e < 0) {
            if (rem < tiles) { e = ee; cnt = c; tmi = rem / TN2; tni = rem % TN2; }
            else             { rem -= tiles; off += c; }
        }
    }
    if (e < 0) return;
    const int m0 = tmi * BM;
    const int n0 = tni * 128;

    const __nv_bfloat16* Ag = g_h  + (size_t)off * INTER;
    const __nv_bfloat16* Bg = g_w2 + (size_t)e * HID * INTER;

    const int warp = tid >> 5, lane = tid & 31;
    const int wm = warp >> 1, wn = warp & 1;
    const int g = lane >> 2, t = lane & 3;

    const uint32_t sb = smem_u32(dsm);
    const uint32_t aLane = (uint32_t)(wm*64 + (lane & 15))*SSTB + (lane >> 4)*16;
    const uint32_t bLane = B_OFFB + (uint32_t)(wn*64 + (lane >> 4)*8 + (lane & 7))*SSTB
                           + ((lane >> 3) & 1)*16;

    float acc[4][8][4];
    #pragma unroll
    for (int i = 0; i < 4; ++i)
        #pragma unroll
        for (int j = 0; j < 8; ++j)
            #pragma unroll
            for (int k = 0; k < 4; ++k) acc[i][j][k] = 0.f;

    auto issue = [&](int kt, int s) {
        const uint32_t base = sb + s * STAGE_BYTES;
        #pragma unroll
        for (int i = 0; i < 8; ++i) {
            int id = tid + i*128;
            if (id < 512) {
                int row = id >> 2, kc = id & 3;
                int gm = m0 + row;
                int sz = (gm < cnt) ? 16 : 0;
                int gmc = (gm < cnt) ? gm : 0;
                cp16(base + row*SSTB + kc*16, Ag + (size_t)gmc*INTER + kt*BK + kc*8, sz);
            } else {
                int b = id - 512;
                int row = b >> 2, kc = b & 3;
                cp16(base + B_OFFB + row*SSTB + kc*16,
                     Bg + (size_t)(n0 + row)*INTER + kt*BK + kc*8, 16);
            }
        }
    };

    const int KT = INTER / BK;  // 44
    issue(0, 0); CP_COMMIT();
    issue(1, 1); CP_COMMIT();
    issue(2, 2); CP_COMMIT();
    issue(3, 3); CP_COMMIT();
    CP_WAIT(2);
    __syncthreads();

    Frag f0, f1;
    ldfrag(f0, sb + aLane, sb + bLane, 0);
    int s_cur = 0;
    for (int kt = 0; kt < KT; ++kt) {
        const uint32_t stg = sb + s_cur * STAGE_BYTES;
        ldfrag(f1, stg + aLane, stg + bLane, 1);
        mma_frag(acc, f0);
        int s_nxt = s_cur + 1; if (s_nxt == NSTAGE) s_nxt = 0;
        if (kt + 4 < KT) {
            int s_iss = s_cur - 1; if (s_iss < 0) s_iss = NSTAGE - 1;
            issue(kt + 4, s_iss);
        }
        CP_COMMIT();
        if (kt + 1 < KT) {
            const uint32_t stg2 = sb + s_nxt * STAGE_BYTES;
            ldfrag(f0, stg2 + aLane, stg2 + bLane, 0);
        }
        mma_frag(acc, f1);
        CP_WAIT(2);
        __syncthreads();
        s_cur = s_nxt;
    }

    // epilogue: round to bf16 then exact f32 upcast (validated numerics)
    #pragma unroll
    for (int im = 0; im < 4; ++im) {
        #pragma unroll
        for (int j = 0; j < 8; ++j) {
            int lm  = wm*64 + im*16 + g;
            int col = n0 + wn*64 + j*8 + t*2;
            if (m0 + lm < cnt) {
                float2* p = (float2*)(out + (size_t)(off + m0 + lm)*HID + col);
                *p = make_float2(bround(acc[im][j][0]), bround(acc[im][j][1]));
            }
            if (m0 + lm + 8 < cnt) {
                float2* p = (float2*)(out + (size_t)(off + m0 + lm + 8)*HID + col);
                *p = make_float2(bround(acc[im][j][2]), bround(acc[im][j][3]));
            }
        }
    }
}

extern "C" void kernel_launch(void* const* d_in, const int* in_sizes, int n_in,
                              void* d_out, int out_size) {
    const float* x      = (const float*)d_in[0];
    const float* w1     = (const float*)d_in[1];
    const float* w2     = (const float*)d_in[2];
    const int*   counts = (const int*)d_in[3];
    float*       out    = (float*)d_out;

    void *pxb, *pw1, *pw2;
    cudaGetSymbolAddress(&pxb, g_xb);
    cudaGetSymbolAddress(&pw1, g_w1);
    cudaGetSymbolAddress(&pw2, g_w2);

    cudaFuncSetAttribute(gemm1_kernel, cudaFuncAttributeMaxDynamicSharedMemorySize, SMEM_BYTES);
    cudaFuncSetAttribute(gemm2_kernel, cudaFuncAttributeMaxDynamicSharedMemorySize, SMEM_BYTES);

    const int n4x  = (TOK * HID) / 4;
    const int n4w1 = (EXPERTS * I2 * HID) / 4;
    const int n4w2 = (EXPERTS * HID * INTER) / 4;

    // Side stream so w2's conversion overlaps gemm1 (gemm1 uses ~5% of HBM).
    // Created fresh each call, never destroyed (destroying a captured stream
    // would invalidate graph capture; no device memory involved).
    cudaStream_t s2;
    cudaEvent_t evF, evJ;
    cudaStreamCreateWithFlags(&s2, cudaStreamNonBlocking);
    cudaEventCreateWithFlags(&evF, cudaEventDisableTiming);
    cudaEventCreateWithFlags(&evJ, cudaEventDisableTiming);

    cvt_kernel<<<(n4x  + 255) / 256, 256>>>((const float4*)x,  (__nv_bfloat162*)pxb, n4x);
    cvt_kernel<<<(n4w1 + 255) / 256, 256>>>((const float4*)w1, (__nv_bfloat162*)pw1, n4w1);

    cudaEventRecord(evF, 0);                   // fork after x/w1 conversions
    cudaStreamWaitEvent(s2, evF, 0);
    cvt_kernel<<<(n4w2 + 255) / 256, 256, 0, s2>>>((const float4*)w2, (__nv_bfloat162*)pw2, n4w2);
    cudaEventRecord(evJ, s2);

    const int maxtm = TOK / BM + EXPERTS;   // 136
    gemm1_kernel<<<maxtm * TN1, 128, SMEM_BYTES>>>(counts);   // overlaps w2 cvt
    cudaStreamWaitEvent(0, evJ, 0);                           // join before gemm2
    gemm2_kernel<<<maxtm * TN2, 128, SMEM_BYTES>>>(counts, out);
}